// round 17
// baseline (speedup 1.0000x reference)
#include <cuda_runtime.h>
#include <cuda_bf16.h>
#include <math_constants.h>
#include <cstdint>

#define NROWS   131072
#define DDIM    64
#define KCODES  1024
#define KC      64           // codes per chunk
#define NCHUNK  16
#define NTHR    256
#define RT      64           // rows per block tile
#define TSTRB   144          // bf16 tile row stride (bytes)
#define GAP_T   4e-3f

// ---- smem byte layout (tiles 64x64 bf16, stride 144) ----
#define OFF_XH    0          // 9216
#define OFF_XL    9216
#define OFF_CH    18432      // C: [code][dim]  (shared by phase A + B)
#define OFF_CL    27648
#define OFF_EH    36864      // E: [row][k]  (reused as reduction scratch)
#define OFF_EL    46080
#define OFF_CN    55296      // 64*4 norms / row sums
#define OFF_FLAGN 55552
#define OFF_FLAGL 55556      // up to 64 ints
#define SMEM_TOTAL 56064

__device__ __forceinline__ uint32_t smem_u32(const void* p) {
    uint32_t a;
    asm("{ .reg .u64 t; cvta.to.shared.u64 t, %1; cvt.u32.u64 %0, t; }" : "=r"(a) : "l"(p));
    return a;
}

#define LDSM_X4(r0,r1,r2,r3, addr) \
    asm volatile("ldmatrix.sync.aligned.m8n8.x4.shared.b16 {%0,%1,%2,%3}, [%4];" \
                 : "=r"(r0),"=r"(r1),"=r"(r2),"=r"(r3) : "r"(addr))
#define LDSM_X4T(r0,r1,r2,r3, addr) \
    asm volatile("ldmatrix.sync.aligned.m8n8.x4.trans.shared.b16 {%0,%1,%2,%3}, [%4];" \
                 : "=r"(r0),"=r"(r1),"=r"(r2),"=r"(r3) : "r"(addr))
#define MMA16816(d, a0,a1,a2,a3, b0,b1) \
    asm volatile("mma.sync.aligned.m16n8k16.row.col.f32.bf16.bf16.f32 " \
                 "{%0,%1,%2,%3}, {%4,%5,%6,%7}, {%8,%9}, {%0,%1,%2,%3};" \
                 : "+f"(d[0]),"+f"(d[1]),"+f"(d[2]),"+f"(d[3]) \
                 : "r"(a0),"r"(a1),"r"(a2),"r"(a3), "r"(b0),"r"(b1))
#define EX2(out, in) \
    asm("ex2.approx.ftz.f32 %0, %1;" : "=f"(out) : "f"(in))

// ---- threefry adds routed to the FMA pipe as IMAD (one = opaque runtime 1) ----
#define ADDR_(d, s, one) \
    asm("mad.lo.u32 %0, %1, %2, %0;" : "+r"(d) : "r"(s), "r"(one))
#define ADDC_(d, imm, one) \
    asm("mad.lo.u32 %0, %1, %2, %0;" : "+r"(d) : "r"(one), "n"(imm))

// threefry2x32, key (0,42) — jax partitionable path: bits[j] = o0^o1, counter (0,j)
// ks1=42, ks2=0x1BD11BDA^42=0x1BD11BF0
__device__ __forceinline__ unsigned threefry_xor_0_42(unsigned c1, unsigned one) {
    unsigned x0 = 0u;
    unsigned x1 = c1 + 42u;
#define TFR(r) { ADDR_(x0, x1, one); x1 = __funnelshift_l(x1, x1, r); x1 ^= x0; }
    TFR(13) TFR(15) TFR(26) TFR(6)
    ADDC_(x0, 42u, one);          ADDC_(x1, 0x1BD11BF1u, one);   // ks1 | ks2+1
    TFR(17) TFR(29) TFR(16) TFR(24)
    ADDC_(x0, 0x1BD11BF0u, one);  ADDC_(x1, 2u, one);            // ks2 | ks0+2
    TFR(13) TFR(15) TFR(26) TFR(6)
    /* x0 += ks0 = 0 (no-op) */   ADDC_(x1, 45u, one);           // ks1+3
    TFR(17) TFR(29) TFR(16) TFR(24)
    ADDC_(x0, 42u, one);          ADDC_(x1, 0x1BD11BF4u, one);   // ks1 | ks2+4
    TFR(13) TFR(15) TFR(26) TFR(6)
    ADDC_(x0, 0x1BD11BF0u, one);  ADDC_(x1, 5u, one);            // ks2 | ks0+5
#undef TFR
    return x0 ^ x1;
}

// u from bits; inner -log(u): fast __logf except winning tail u>=0.99 (log1pf).
__device__ __forceinline__ float neglog_u(unsigned bits) {
    float u = (float)(bits >> 9) * 1.1920928955078125e-7f;
    u = fmaxf(u, 1.17549435e-38f);
    float v;
    if (u < 0.99f) v = -__logf(u);
    else           v = -log1pf(u - 1.0f);     // rare (~1% of lanes)
    return v;
}

__device__ __forceinline__ void split_bf16(float v, unsigned short& h, unsigned short& l) {
    __nv_bfloat16 hb = __float2bfloat16(v);
    h = __bfloat16_as_ushort(hb);
    l = __bfloat16_as_ushort(__float2bfloat16(v - __bfloat162float(hb)));
}

__global__ __launch_bounds__(NTHR, 4)
void fused_quantize(const float* __restrict__ x,
                    const float* __restrict__ cbg,
                    const float* __restrict__ temp,
                    float* __restrict__ out,
                    int out_size,
                    unsigned one)          // opaque 1: keeps threefry adds as IMAD
{
    extern __shared__ char smem[];
    const uint32_t sb = smem_u32(smem);
    float* cnf = (float*)(smem + OFF_CN);

    const int tid  = threadIdx.x;
    const int wid  = tid >> 5;         // 0..7
    const int lane = tid & 31;
    const int wr   = wid & 3;          // row group (16 rows)
    const int wc   = wid >> 2;         // col half (32)
    const int rbase = blockIdx.x * RT;
    const float invT = 1.0f / temp[0];
    const float c1   = invT * 1.4426950408889634f;   // invT*log2(e)
    const bool has_ids = (out_size >= NROWS*DDIM + NROWS);

    if (tid == 0) *(int*)(smem + OFF_FLAGN) = 0;

    // ldmatrix lane addressing
    const int a_row = wr*16 + (lane & 7) + ((lane >> 3) & 1)*8;
    const int a_col = ((lane >> 4) & 1) * 16;
    const uint32_t aoff = (uint32_t)(a_row*TSTRB + a_col);
    // phase-A B x4 (non-trans on C[code][dim]): r0,r1 = ntile0, r2,r3 = ntile1
    const uint32_t bA4 = (uint32_t)(((lane & 7) + ((lane >> 4) & 1)*8)*TSTRB
                                    + ((lane >> 3) & 1)*16);
    // phase-B B x4 (trans on C[code][dim]): rows = codes(k), cols = dims(n)
    const uint32_t bB4 = (uint32_t)(((lane & 7) + ((lane >> 3) & 1)*8)*TSTRB
                                    + ((lane >> 4) & 1)*16);
    const int rowA  = wr*16 + (lane >> 2);

    // ---- build X bf16 hi/lo tiles [row][dim] (once; coalesced) ----
#pragma unroll
    for (int i = 0; i < 4; i++) {
        int q = tid + i*NTHR;          // 1024 float4s
        int row = q >> 4;
        int d4  = (q & 15) * 4;
        float4 v = *(const float4*)(x + (size_t)(rbase + row)*DDIM + d4);
        unsigned short h0,h1,h2,h3,l0,l1,l2,l3;
        split_bf16(v.x,h0,l0); split_bf16(v.y,h1,l1);
        split_bf16(v.z,h2,l2); split_bf16(v.w,h3,l3);
        uint32_t base = (uint32_t)(row*TSTRB + d4*2);
        *(uint2*)(smem + OFF_XH + base) =
            make_uint2((uint32_t)h0 | ((uint32_t)h1<<16), (uint32_t)h2 | ((uint32_t)h3<<16));
        *(uint2*)(smem + OFF_XL + base) =
            make_uint2((uint32_t)l0 | ((uint32_t)l1<<16), (uint32_t)l2 | ((uint32_t)l3<<16));
    }

    // persistent per-lane state: 2 rows (rowA, rowA+8)
    float sum2[2] = {0.f, 0.f};
    float pb1[2] = {-CUDART_INF_F, -CUDART_INF_F};
    float pb2[2] = {-CUDART_INF_F, -CUDART_INF_F};
    int   pi1[2] = {0, 0};
    float bacc[4][4];
#pragma unroll
    for (int nt = 0; nt < 4; nt++)
#pragma unroll
        for (int q = 0; q < 4; q++) bacc[nt][q] = 0.f;

    for (int c = 0; c < NCHUNK; c++) {
        const int kb = c * KC;
        __syncthreads();   // prev chunk's C/E consumed

        // ---- build C [code][dim] bf16 hi/lo tile ----
        {
            const int code = tid & 63;
            const int dg   = tid >> 6;     // 16-dim group (0..3)
            const float* src = cbg + (size_t)(kb + code)*DDIM + dg*16;
            unsigned short hs[16], ls[16];
#pragma unroll
            for (int i = 0; i < 4; i++) {
                float4 v = ((const float4*)src)[i];
                split_bf16(v.x, hs[i*4+0], ls[i*4+0]);
                split_bf16(v.y, hs[i*4+1], ls[i*4+1]);
                split_bf16(v.z, hs[i*4+2], ls[i*4+2]);
                split_bf16(v.w, hs[i*4+3], ls[i*4+3]);
            }
            uint32_t hp[8], lp[8];
#pragma unroll
            for (int i = 0; i < 8; i++) {
                hp[i] = (uint32_t)hs[2*i] | ((uint32_t)hs[2*i+1] << 16);
                lp[i] = (uint32_t)ls[2*i] | ((uint32_t)ls[2*i+1] << 16);
            }
            uint32_t cbase = (uint32_t)(code*TSTRB + dg*32);
            *(uint4*)(smem + OFF_CH + cbase)      = make_uint4(hp[0],hp[1],hp[2],hp[3]);
            *(uint4*)(smem + OFF_CH + cbase + 16) = make_uint4(hp[4],hp[5],hp[6],hp[7]);
            *(uint4*)(smem + OFF_CL + cbase)      = make_uint4(lp[0],lp[1],lp[2],lp[3]);
            *(uint4*)(smem + OFF_CL + cbase + 16) = make_uint4(lp[4],lp[5],lp[6],lp[7]);
        }
        // ---- exact fp32 code norms from gmem ----
        if (tid < KC) {
            const float* src = cbg + (size_t)(kb + tid)*DDIM;
            float s = 0.f;
#pragma unroll
            for (int i = 0; i < 16; i++) {
                float4 v = ((const float4*)src)[i];
                s = fmaf(v.x, v.x, s); s = fmaf(v.y, v.y, s);
                s = fmaf(v.z, v.z, s); s = fmaf(v.w, v.w, s);
            }
            cnf[tid] = s;
        }
        __syncthreads();

        // ========== Phase A (tensor): S = X(64x64) * C^T(64x64), 3-split ==========
        float sacc[4][4];
#pragma unroll
        for (int nt = 0; nt < 4; nt++)
#pragma unroll
            for (int q = 0; q < 4; q++) sacc[nt][q] = 0.f;

#pragma unroll
        for (int ks = 0; ks < 4; ks++) {
            const int k0b = ks * 32;          // 16 dims * 2 bytes
            uint32_t ah0,ah1,ah2,ah3, al0,al1,al2,al3;
            LDSM_X4(ah0,ah1,ah2,ah3, sb + OFF_XH + aoff + k0b);
            LDSM_X4(al0,al1,al2,al3, sb + OFF_XL + aoff + k0b);
#pragma unroll
            for (int pr = 0; pr < 2; pr++) {
                uint32_t boff = bA4 + (uint32_t)((wc*32 + pr*16)*TSTRB) + (uint32_t)k0b;
                uint32_t bh0,bh1,bh2,bh3, bl0,bl1,bl2,bl3;
                LDSM_X4(bh0,bh1,bh2,bh3, sb + OFF_CH + boff);
                LDSM_X4(bl0,bl1,bl2,bl3, sb + OFF_CL + boff);
                MMA16816(sacc[pr*2+0], ah0,ah1,ah2,ah3, bh0,bh1);
                MMA16816(sacc[pr*2+0], ah0,ah1,ah2,ah3, bl0,bl1);
                MMA16816(sacc[pr*2+0], al0,al1,al2,al3, bh0,bh1);
                MMA16816(sacc[pr*2+1], ah0,ah1,ah2,ah3, bh2,bh3);
                MMA16816(sacc[pr*2+1], ah0,ah1,ah2,ah3, bl2,bl3);
                MMA16816(sacc[pr*2+1], al0,al1,al2,al3, bh2,bh3);
            }
        }

        // ---- epilogue on fragments: top2, gumbel, exp2, E-tile write ----
#pragma unroll
        for (int slot = 0; slot < 2; slot++) {
            const int row = rowA + slot*8;
            const unsigned fb = (unsigned)(rbase + row)*1024u + (unsigned)kb;
            const uint32_t ebase = (uint32_t)(row*TSTRB + wc*64 + (lane&3)*4);
#pragma unroll
            for (int nt = 0; nt < 4; nt++) {
                const int c0 = wc*32 + nt*8 + (lane&3)*2;
                float2 cnv = *(float2*)(smem + OFF_CN + c0*4);
                float s0 = fmaf(2.0f, sacc[nt][slot*2+0], -cnv.x);
                float s1 = fmaf(2.0f, sacc[nt][slot*2+1], -cnv.y);
                if (s0 > pb1[slot]) { pb2[slot] = pb1[slot]; pb1[slot] = s0; pi1[slot] = kb + c0; }
                else if (s0 > pb2[slot]) pb2[slot] = s0;
                if (s1 > pb1[slot]) { pb2[slot] = pb1[slot]; pb1[slot] = s1; pi1[slot] = kb + c0 + 1; }
                else if (s1 > pb2[slot]) pb2[slot] = s1;
                float v0 = neglog_u(threefry_xor_0_42(fb + (unsigned)c0, one));
                float v1 = neglog_u(threefry_xor_0_42(fb + (unsigned)c0 + 1u, one));
                // e = exp((s - log v)/T) = exp2(s*c1 - log2(v)*invT)
                float e0, e1;
                EX2(e0, fmaf(__log2f(v0), -invT, s0*c1));
                EX2(e1, fmaf(__log2f(v1), -invT, s1*c1));
                sum2[slot] += e0 + e1;
                unsigned short h0,h1,l0,l1;
                split_bf16(e0,h0,l0); split_bf16(e1,h1,l1);
                *(uint32_t*)(smem + OFF_EH + ebase + nt*16) = (uint32_t)h0 | ((uint32_t)h1<<16);
                *(uint32_t*)(smem + OFF_EL + ebase + nt*16) = (uint32_t)l0 | ((uint32_t)l1<<16);
            }
        }
        __syncthreads();   // E visible

        // ========== Phase B (tensor): emb_raw += E(64x64) * C(64x64) ==========
#pragma unroll
        for (int ks = 0; ks < 4; ks++) {
            const int k0 = ks * 16;
            uint32_t ah0,ah1,ah2,ah3, al0,al1,al2,al3;
            LDSM_X4(ah0,ah1,ah2,ah3, sb + OFF_EH + aoff + k0*2);
            LDSM_X4(al0,al1,al2,al3, sb + OFF_EL + aoff + k0*2);
#pragma unroll
            for (int pr = 0; pr < 2; pr++) {
                uint32_t boff = bB4 + (uint32_t)(k0*TSTRB) + (uint32_t)((wc*32 + pr*16)*2);
                uint32_t bh0,bh1,bh2,bh3, bl0,bl1,bl2,bl3;
                LDSM_X4T(bh0,bh1,bh2,bh3, sb + OFF_CH + boff);
                LDSM_X4T(bl0,bl1,bl2,bl3, sb + OFF_CL + boff);
                MMA16816(bacc[pr*2+0], ah0,ah1,ah2,ah3, bh0,bh1);
                MMA16816(bacc[pr*2+0], ah0,ah1,ah2,ah3, bl0,bl1);
                MMA16816(bacc[pr*2+0], al0,al1,al2,al3, bh0,bh1);
                MMA16816(bacc[pr*2+1], ah0,ah1,ah2,ah3, bh2,bh3);
                MMA16816(bacc[pr*2+1], ah0,ah1,ah2,ah3, bl2,bl3);
                MMA16816(bacc[pr*2+1], al0,al1,al2,al3, bh2,bh3);
            }
        }
    }
    __syncthreads();   // all tiles consumed; EH reusable as scratch

    // ---- per-row reduction: 8 partials (4 quad-lanes x 2 wc) ----
    float* rsum = (float*)(smem + OFF_EH);   // [8][64]
    float* rb1  = rsum + 8*64;
    float* rb2  = rb1  + 8*64;
    int*   ri1  = (int*)(rb2 + 8*64);
    const int p = wc*4 + (lane & 3);
#pragma unroll
    for (int slot = 0; slot < 2; slot++) {
        int row = rowA + slot*8;
        rsum[p*64 + row] = sum2[slot];
        rb1 [p*64 + row] = pb1[slot];
        rb2 [p*64 + row] = pb2[slot];
        ri1 [p*64 + row] = pi1[slot];
    }
    __syncthreads();
    if (tid < RT) {
        const int r = tid;
        float s = 0.f, b = -CUDART_INF_F, b2 = -CUDART_INF_F;
        int bi = 0;
#pragma unroll
        for (int t = 0; t < 8; t++) {
            s += rsum[t*64 + r];
            float v1 = rb1[t*64 + r];
            float v2 = rb2[t*64 + r];
            int   ii = ri1[t*64 + r];
            if (v1 > b || (v1 == b && ii < bi)) {
                b2 = fmaxf(b, v2);
                b = v1; bi = ii;
            } else {
                b2 = fmaxf(b2, v1);
            }
        }
        cnf[r] = s;
        if (b - b2 < GAP_T) {
            int idx = atomicAdd((int*)(smem + OFF_FLAGN), 1);
            ((int*)(smem + OFF_FLAGL))[idx] = r;
        } else if (has_ids) {
            out[NROWS*DDIM + (rbase + r)] = (float)bi;
        }
    }
    __syncthreads();

    // ---- write emb = bacc / sum ----
    {
        const int row_b = rowA + 8;
        const float inva = 1.0f / cnf[rowA];
        const float invb = 1.0f / cnf[row_b];
        float* oa = out + (size_t)(rbase + rowA)*DDIM;
        float* ob = out + (size_t)(rbase + row_b)*DDIM;
#pragma unroll
        for (int nt = 0; nt < 4; nt++) {
            int col = wc*32 + nt*8 + (lane & 3)*2;
            *(float2*)(oa + col) = make_float2(bacc[nt][0]*inva, bacc[nt][1]*inva);
            *(float2*)(ob + col) = make_float2(bacc[nt][2]*invb, bacc[nt][3]*invb);
        }
    }

    // ---- exact fp32 argmax fix-up for ambiguous rows (one warp per row) ----
    {
        const int nf = *(volatile int*)(smem + OFF_FLAGN);
        const int* fl = (const int*)(smem + OFF_FLAGL);
        for (int f = wid; f < nf; f += 8) {
            const int r = fl[f];
            const float* xr = x + (size_t)(rbase + r)*DDIM;
            float best = -CUDART_INF_F;
            int bi = 0;
            for (int k = lane; k < KCODES; k += 32) {
                const float* cr = cbg + (size_t)k*DDIM;
                float dot = 0.f, nrm = 0.f;
#pragma unroll
                for (int i = 0; i < 16; i++) {
                    float4 cv = ((const float4*)cr)[i];
                    float4 xv = ((const float4*)xr)[i];
                    dot = fmaf(xv.x, cv.x, dot); nrm = fmaf(cv.x, cv.x, nrm);
                    dot = fmaf(xv.y, cv.y, dot); nrm = fmaf(cv.y, cv.y, nrm);
                    dot = fmaf(xv.z, cv.z, dot); nrm = fmaf(cv.z, cv.z, nrm);
                    dot = fmaf(xv.w, cv.w, dot); nrm = fmaf(cv.w, cv.w, nrm);
                }
                float sv = fmaf(2.0f, dot, -nrm);
                if (sv > best) { best = sv; bi = k; }
            }
#pragma unroll
            for (int off = 16; off; off >>= 1) {
                float ob = __shfl_down_sync(0xffffffffu, best, off);
                int  obi = __shfl_down_sync(0xffffffffu, bi, off);
                if (ob > best || (ob == best && obi < bi)) { best = ob; bi = obi; }
            }
            if (lane == 0 && has_ids)
                out[NROWS*DDIM + (rbase + r)] = (float)bi;
        }
    }
}

extern "C" void kernel_launch(void* const* d_in, const int* in_sizes, int n_in,
                              void* d_out, int out_size) {
    const float* x  = (const float*)d_in[0];
    const float* cb = (const float*)d_in[1];
    const float* t  = (const float*)d_in[2];
    float* out = (float*)d_out;

    unsigned one = (n_in > 0) ? 1u : 2u;   // always 1; opaque to the compiler device-side

    cudaFuncSetAttribute(fused_quantize,
                         cudaFuncAttributeMaxDynamicSharedMemorySize, SMEM_TOTAL);
    fused_quantize<<<NROWS/RT, NTHR, SMEM_TOTAL>>>(x, cb, t, out, out_size, one);
}